// round 11
// baseline (speedup 1.0000x reference)
#include <cuda_runtime.h>
#include <cstdint>

#define HH 512
#define WW 512
#define CCH 3
#define SS 2
#define AA 3
#define NB 8
#define BB 2
#define SKS 9
#define AKS 7

__device__ float g_conv[CCH * SS * HH * WW];   // sigma-blurred maps

// ---------------------------------------------------------------------------
// Fused sigma blur: clip + separable 9-tap (both sigmas) per 32x32 tile.
// 1D weights (= row sums of the 2D kernel, exact rank-1) derived per CTA.
// ---------------------------------------------------------------------------
#define STW 32
#define STH 32
#define SIN 40

__global__ __launch_bounds__(256) void k_sigma(const float* __restrict__ im,
                                               const float* __restrict__ sig2d) {
    __shared__ float s_in[SIN][SIN];
    __shared__ float s_ht[SS][SIN][STW + 1];
    __shared__ float wsig[SS * 5];
    int tid = threadIdx.x;
    int c = blockIdx.z;
    int gy0 = blockIdx.y * STH, gx0 = blockIdx.x * STW;

    if (tid < SS * 5) {
        int s = tid / 5, k = tid % 5;
        float sum = 0.f;
        for (int j = 0; j < SKS; j++) sum += __ldg(&sig2d[(s * SKS + k) * SKS + j]);
        wsig[tid] = sum;
    }
    for (int i = tid; i < SIN * SIN; i += 256) {
        int r = i / SIN, q = i - r * SIN;
        int gy = gy0 + r - 4, gx = gx0 + q - 4;
        float v = 0.f;
        if (gy >= 0 && gy < HH && gx >= 0 && gx < WW) {
            v = __ldg(&im[((size_t)gy * WW + gx) * CCH + c]);
            v = fminf(fmaxf(v, 0.f), 1.f);
        }
        s_in[r][q] = v;
    }
    __syncthreads();
    float w[SS][5];
#pragma unroll
    for (int s = 0; s < SS; s++)
#pragma unroll
        for (int k = 0; k < 5; k++) w[s][k] = wsig[s * 5 + k];

    for (int i = tid; i < SIN * STW; i += 256) {
        int r = i / STW, x = i - r * STW;
        const float* row = &s_in[r][x];
        float p0 = row[0] + row[8], p1 = row[1] + row[7];
        float p2 = row[2] + row[6], p3 = row[3] + row[5];
        float m = row[4];
#pragma unroll
        for (int s = 0; s < SS; s++) {
            float acc = w[s][4] * m;
            acc = fmaf(w[s][0], p0, acc);
            acc = fmaf(w[s][1], p1, acc);
            acc = fmaf(w[s][2], p2, acc);
            acc = fmaf(w[s][3], p3, acc);
            s_ht[s][r][x] = acc;
        }
    }
    __syncthreads();

    for (int i = tid; i < STH * STW; i += 256) {
        int y = i / STW, x = i - y * STW;
#pragma unroll
        for (int s = 0; s < SS; s++) {
            const float* col = &s_ht[s][y][x];
            const int L = STW + 1;
            float p0 = col[0] + col[8 * L], p1 = col[1 * L] + col[7 * L];
            float p2 = col[2 * L] + col[6 * L], p3 = col[3 * L] + col[5 * L];
            float m = col[4 * L];
            float acc = w[s][4] * m;
            acc = fmaf(w[s][0], p0, acc);
            acc = fmaf(w[s][1], p1, acc);
            acc = fmaf(w[s][2], p2, acc);
            acc = fmaf(w[s][3], p3, acc);
            g_conv[(((size_t)c * SS + s) * HH + gy0 + y) * WW + gx0 + x] = acc;
        }
    }
}

// ---------------------------------------------------------------------------
// Packed f32x2 + shuffle helpers
// ---------------------------------------------------------------------------
union F2U { float2 f; unsigned long long u; };
__device__ __forceinline__ float2 ffma2(float2 a, float2 b, float2 c) {
    F2U A, B, C, D; A.f = a; B.f = b; C.f = c;
    asm("fma.rn.f32x2 %0, %1, %2, %3;" : "=l"(D.u) : "l"(A.u), "l"(B.u), "l"(C.u));
    return D.f;
}
__device__ __forceinline__ float2 fmul2(float2 a, float2 b) {
    F2U A, B, D; A.f = a; B.f = b;
    asm("mul.rn.f32x2 %0, %1, %2;" : "=l"(D.u) : "l"(A.u), "l"(B.u));
    return D.f;
}
__device__ __forceinline__ float2 fadd2(float2 a, float2 b) {
    F2U A, B, D; A.f = a; B.f = b;
    asm("add.rn.f32x2 %0, %1, %2;" : "=l"(D.u) : "l"(A.u), "l"(B.u));
    return D.f;
}
__device__ __forceinline__ float2 shfl2(float2 v, int lane) {
    float2 r;
    r.x = __shfl_sync(0xffffffffu, v.x, lane);
    r.y = __shfl_sync(0xffffffffu, v.y, lane);
    return r;
}

// ---------------------------------------------------------------------------
// K2: warp w owns x in [8w, 8w+16); lane l: p = l&3 (binpair), xi = l>>2.
// iso lives in registers (v1 @ x=8w+xi, v2 @ x=8w+8+xi); horizontal taps via
// shuffles; vertical in register rings (a0,a1) + thread-private smem ring
// (a2). No barriers in the row loop. Stores 256B-coalesced STG.64.
// ---------------------------------------------------------------------------
#define W_T 64
#define H_T 32
#define RIN 38           // H_T + 6 input rows
#define POSP 72          // padded conv row (needs 70; lanes read up to 71)

struct SMemL {
    float  conv[RIN * POSP];       // 10944 B
    float2 h2[7][256];             // 14336 B, alpha2 hconv ring
    float  wal[AA * 4];
};

__global__ __launch_bounds__(256, 3) void k_loi(const float* __restrict__ al2d,
                                                const float* __restrict__ centers,
                                                const float* __restrict__ betas,
                                                float* __restrict__ out) {
    __shared__ SMemL sm;
    int tid = threadIdx.x;
    int l = tid & 31, w = tid >> 5;
    int p = l & 3, xi = l >> 2;
    int x1 = 8 * w + xi;           // iso position 1 (also this thread's output x)
    int z = blockIdx.z;
    int c = z / SS, s = z % SS;
    int gy0 = blockIdx.y * H_T;
    int gx0 = blockIdx.x * W_T;
    const float* convmap = g_conv + (size_t)z * HH * WW;

    if (tid < AA * 4) {
        int a = tid >> 2, k = tid & 3;
        float sum = 0.f;
        for (int j = 0; j < AKS; j++) sum += __ldg(&al2d[(a * AKS + k) * AKS + j]);
        sm.wal[tid] = sum;
    }
    // conv slab (halo 3; OOB/pad -> sentinel so iso == 0 exactly)
    for (int i = tid; i < RIN * POSP; i += 256) {
        int r = i / POSP, q = i - r * POSP;
        int gy = gy0 + r - 3, gx = gx0 + q - 3;
        sm.conv[i] = (q < 70 && gy >= 0 && gy < HH && gx >= 0 && gx < WW)
                     ? __ldg(&convmap[(size_t)gy * WW + gx]) : -1e30f;
    }
    float cn0 = __ldg(&centers[2 * p]);
    float cn1 = __ldg(&centers[2 * p + 1]);
    __syncthreads();

    float2 wk[AA][4];
#pragma unroll
    for (int a = 0; a < AA; a++)
#pragma unroll
        for (int k = 0; k < 4; k++) {
            float wv = sm.wal[a * 4 + k];
            wk[a][k] = make_float2(wv, wv);
        }

    const size_t ASTR = (size_t)BB * SS * CCH * HH * WW * (NB / 2);  // float2

#pragma unroll 1
    for (int b = 0; b < BB; b++) {
        float invb = 1.f / __ldg(&betas[b]);
        float nrm = 0.3989422804014327f * invb;
        float kf = -0.5f * invb * invb;

        float2 acc[2][7];
        float2* outb = (float2*)out +
                       (size_t)((b * SS + s) * CCH + c) * (HH * WW * (NB / 2));

#pragma unroll 1
        for (int r7 = 0; r7 < 6; r7++) {
#pragma unroll
            for (int rr = 0; rr < 7; rr++) {
                int row = r7 * 7 + rr;
                if (row < RIN) {
                    // ---- iso in registers at x1 and x1+8 ----
                    float cva = sm.conv[row * POSP + x1];
                    float cvb = sm.conv[row * POSP + x1 + 8];
                    float da0 = cva - cn0, da1 = cva - cn1;
                    float db0 = cvb - cn0, db1 = cvb - cn1;
                    float2 v1, v2;
                    v1.x = nrm * __expf(kf * da0 * da0);
                    v1.y = nrm * __expf(kf * da1 * da1);
                    v2.x = nrm * __expf(kf * db0 * db0);
                    v2.y = nrm * __expf(kf * db1 * db1);

                    // ---- horizontal taps via shuffle (j = 1..6) ----
                    float2 tp[7];
                    tp[0] = v1;
#pragma unroll
                    for (int j = 1; j < 7; j++) {
                        int idx = (l + 4 * j) & 31;
                        float2 t1 = shfl2(v1, idx);
                        float2 t2 = shfl2(v2, idx);
                        tp[j] = (xi + j < 8) ? t1 : t2;
                    }
                    float2 s0 = fadd2(tp[0], tp[6]);
                    float2 s1 = fadd2(tp[1], tp[5]);
                    float2 s2 = fadd2(tp[2], tp[4]);
                    float2 m = tp[3];

                    float2 hv0 = fmul2(wk[0][3], m);
                    float2 hv1 = fmul2(wk[1][3], m);
                    float2 hv2 = fmul2(wk[2][3], m);
                    hv0 = ffma2(wk[0][0], s0, hv0);
                    hv1 = ffma2(wk[1][0], s0, hv1);
                    hv2 = ffma2(wk[2][0], s0, hv2);
                    hv0 = ffma2(wk[0][1], s1, hv0);
                    hv1 = ffma2(wk[1][1], s1, hv1);
                    hv2 = ffma2(wk[2][1], s1, hv2);
                    hv0 = ffma2(wk[0][2], s2, hv0);
                    hv1 = ffma2(wk[1][2], s2, hv1);
                    hv2 = ffma2(wk[2][2], s2, hv2);

                    // alpha2: thread-private smem ring
                    sm.h2[rr][tid] = hv2;

                    // alphas 0,1: register scatter rings (stale slots are
                    // re-initialized at t==0 before any store)
#pragma unroll
                    for (int t = 0; t < 7; t++) {
                        const int slot = ((rr - t) % 7 + 7) % 7;
                        const int wi = (t < 4) ? t : 6 - t;
                        if (t == 0) {
                            acc[0][slot] = fmul2(wk[0][wi], hv0);
                            acc[1][slot] = fmul2(wk[1][wi], hv1);
                        } else {
                            acc[0][slot] = ffma2(wk[0][wi], hv0, acc[0][slot]);
                            acc[1][slot] = ffma2(wk[1][wi], hv1, acc[1][slot]);
                        }
                    }

                    // ---- completed output row y = row - 6 ----
                    if (row >= 6) {
                        const int slot = (rr + 1) % 7;
                        float2 g0 = sm.h2[(rr + 1) % 7][tid];
                        float2 g1 = sm.h2[(rr + 2) % 7][tid];
                        float2 g2 = sm.h2[(rr + 3) % 7][tid];
                        float2 g3 = sm.h2[(rr + 4) % 7][tid];
                        float2 g4 = sm.h2[(rr + 5) % 7][tid];
                        float2 g5 = sm.h2[(rr + 6) % 7][tid];
                        float2 sA = fadd2(g0, hv2);
                        float2 sB = fadd2(g1, g5);
                        float2 sC = fadd2(g2, g4);
                        float2 o2 = fmul2(wk[2][3], g3);
                        o2 = ffma2(wk[2][0], sA, o2);
                        o2 = ffma2(wk[2][1], sB, o2);
                        o2 = ffma2(wk[2][2], sC, o2);

                        size_t off = ((size_t)(gy0 + row - 6) * WW + gx0 + x1) * (NB / 2) + p;
                        outb[off] = acc[0][slot];
                        outb[off + ASTR] = acc[1][slot];
                        outb[off + 2 * ASTR] = o2;
                    }
                }
            }
        }
    }
}

// ---------------------------------------------------------------------------
extern "C" void kernel_launch(void* const* d_in, const int* in_sizes, int n_in,
                              void* d_out, int out_size) {
    const float* im      = (const float*)d_in[0];   // (512,512,3)
    const float* sig2d   = (const float*)d_in[1];   // (2,9,9)
    const float* al2d    = (const float*)d_in[2];   // (3,7,7)
    const float* centers = (const float*)d_in[3];   // (8,)
    const float* betas   = (const float*)d_in[4];   // (2,)
    float* out = (float*)d_out;

    dim3 gs(WW / STW, HH / STH, CCH);
    k_sigma<<<gs, 256>>>(im, sig2d);
    dim3 g(WW / W_T, HH / H_T, CCH * SS);
    k_loi<<<g, 256>>>(al2d, centers, betas, out);
}

// round 12
// speedup vs baseline: 1.3612x; 1.3612x over previous
#include <cuda_runtime.h>
#include <cstdint>

#define HH 512
#define WW 512
#define CCH 3
#define SS 2
#define AA 3
#define NB 8
#define BB 2
#define SKS 9
#define AKS 7

__device__ float g_conv[CCH * SS * HH * WW];   // sigma-blurred maps

// ---------------------------------------------------------------------------
// Fused sigma blur: clip + separable 9-tap (both sigmas) per 32x32 tile.
// 1D weights (= row sums of the 2D kernel, exact rank-1) derived per CTA.
// ---------------------------------------------------------------------------
#define STW 32
#define STH 32
#define SIN 40

__global__ __launch_bounds__(256) void k_sigma(const float* __restrict__ im,
                                               const float* __restrict__ sig2d) {
    __shared__ float s_in[SIN][SIN];
    __shared__ float s_ht[SS][SIN][STW + 1];
    __shared__ float wsig[SS * 5];
    int tid = threadIdx.x;
    int c = blockIdx.z;
    int gy0 = blockIdx.y * STH, gx0 = blockIdx.x * STW;

    if (tid < SS * 5) {
        int s = tid / 5, k = tid % 5;
        float sum = 0.f;
        for (int j = 0; j < SKS; j++) sum += __ldg(&sig2d[(s * SKS + k) * SKS + j]);
        wsig[tid] = sum;
    }
    for (int i = tid; i < SIN * SIN; i += 256) {
        int r = i / SIN, q = i - r * SIN;
        int gy = gy0 + r - 4, gx = gx0 + q - 4;
        float v = 0.f;
        if (gy >= 0 && gy < HH && gx >= 0 && gx < WW) {
            v = __ldg(&im[((size_t)gy * WW + gx) * CCH + c]);
            v = fminf(fmaxf(v, 0.f), 1.f);
        }
        s_in[r][q] = v;
    }
    __syncthreads();
    float w[SS][5];
#pragma unroll
    for (int s = 0; s < SS; s++)
#pragma unroll
        for (int k = 0; k < 5; k++) w[s][k] = wsig[s * 5 + k];

    for (int i = tid; i < SIN * STW; i += 256) {
        int r = i / STW, x = i - r * STW;
        const float* row = &s_in[r][x];
        float p0 = row[0] + row[8], p1 = row[1] + row[7];
        float p2 = row[2] + row[6], p3 = row[3] + row[5];
        float m = row[4];
#pragma unroll
        for (int s = 0; s < SS; s++) {
            float acc = w[s][4] * m;
            acc = fmaf(w[s][0], p0, acc);
            acc = fmaf(w[s][1], p1, acc);
            acc = fmaf(w[s][2], p2, acc);
            acc = fmaf(w[s][3], p3, acc);
            s_ht[s][r][x] = acc;
        }
    }
    __syncthreads();

    for (int i = tid; i < STH * STW; i += 256) {
        int y = i / STW, x = i - y * STW;
#pragma unroll
        for (int s = 0; s < SS; s++) {
            const float* col = &s_ht[s][y][x];
            const int L = STW + 1;
            float p0 = col[0] + col[8 * L], p1 = col[1 * L] + col[7 * L];
            float p2 = col[2 * L] + col[6 * L], p3 = col[3 * L] + col[5 * L];
            float m = col[4 * L];
            float acc = w[s][4] * m;
            acc = fmaf(w[s][0], p0, acc);
            acc = fmaf(w[s][1], p1, acc);
            acc = fmaf(w[s][2], p2, acc);
            acc = fmaf(w[s][3], p3, acc);
            g_conv[(((size_t)c * SS + s) * HH + gy0 + y) * WW + gx0 + x] = acc;
        }
    }
}

// ---------------------------------------------------------------------------
// Packed f32x2 helpers
// ---------------------------------------------------------------------------
union F2U { float2 f; unsigned long long u; };
__device__ __forceinline__ float2 ffma2(float2 a, float2 b, float2 c) {
    F2U A, B, C, D; A.f = a; B.f = b; C.f = c;
    asm("fma.rn.f32x2 %0, %1, %2, %3;" : "=l"(D.u) : "l"(A.u), "l"(B.u), "l"(C.u));
    return D.f;
}
__device__ __forceinline__ float2 fmul2(float2 a, float2 b) {
    F2U A, B, D; A.f = a; B.f = b;
    asm("mul.rn.f32x2 %0, %1, %2;" : "=l"(D.u) : "l"(A.u), "l"(B.u));
    return D.f;
}
__device__ __forceinline__ float2 fadd2(float2 a, float2 b) {
    F2U A, B, D; A.f = a; B.f = b;
    asm("add.rn.f32x2 %0, %1, %2;" : "=l"(D.u) : "l"(A.u), "l"(B.u));
    return D.f;
}

// ---------------------------------------------------------------------------
// K2: grid z = (c,s,b) -> 12 planes, one beta per CTA. Warp w owns x in
// [8w, 8w+8); lane l: p = l&3 (binpair), xi = l>>2. Each warp produces the
// 16 iso positions its window needs into a warp-PRIVATE parity-buffered
// slab -> only __syncwarp per row, zero CTA barriers in the row loop.
// Vertical: register rings (a0, a1) + thread-private smem ring (a2).
// ---------------------------------------------------------------------------
#define W_T 64
#define H_T 32
#define RIN 38           // H_T + 6 input rows
#define POSP 72          // padded conv row (lanes read up to 71; pad=sentinel)

struct SMemL {
    float  conv[RIN * POSP];       // 10944 B
    float2 priv[2][8][64];         // 8192 B, [row parity][warp][pos*4+p]
    float2 h2[7][256];             // 14336 B, alpha2 hconv ring
    float  wal[AA * 4];
};

__global__ __launch_bounds__(256, 3) void k_loi(const float* __restrict__ al2d,
                                                const float* __restrict__ centers,
                                                const float* __restrict__ betas,
                                                float* __restrict__ out) {
    __shared__ SMemL sm;
    int tid = threadIdx.x;
    int l = tid & 31, w = tid >> 5;
    int p = l & 3, xi = l >> 2;
    int z = blockIdx.z;
    int b = z % BB;
    int cs = z / BB;
    int c = cs / SS, s = cs % SS;
    int gy0 = blockIdx.y * H_T;
    int gx0 = blockIdx.x * W_T;
    const float* convmap = g_conv + (size_t)cs * HH * WW;

    if (tid < AA * 4) {
        int a = tid >> 2, k = tid & 3;
        float sum = 0.f;
        for (int j = 0; j < AKS; j++) sum += __ldg(&al2d[(a * AKS + k) * AKS + j]);
        sm.wal[tid] = sum;
    }
    // conv slab (halo 3; OOB/pad -> sentinel so iso == 0 exactly)
    for (int i = tid; i < RIN * POSP; i += 256) {
        int r = i / POSP, q = i - r * POSP;
        int gy = gy0 + r - 3, gx = gx0 + q - 3;
        sm.conv[i] = (q < 70 && gy >= 0 && gy < HH && gx >= 0 && gx < WW)
                     ? __ldg(&convmap[(size_t)gy * WW + gx]) : -1e30f;
    }
    float cn0 = __ldg(&centers[2 * p]);
    float cn1 = __ldg(&centers[2 * p + 1]);
    __syncthreads();

    float2 wk[AA][4];
#pragma unroll
    for (int a = 0; a < AA; a++)
#pragma unroll
        for (int k = 0; k < 4; k++) {
            float wv = sm.wal[a * 4 + k];
            wk[a][k] = make_float2(wv, wv);
        }

    const size_t ASTR = (size_t)BB * SS * CCH * HH * WW * (NB / 2);  // float2

    float invb = 1.f / __ldg(&betas[b]);
    float nrm = 0.3989422804014327f * invb;
    float kf = -0.5f * invb * invb;

    float2 acc[2][7];
    float2* outb = (float2*)out +
                   (size_t)((b * SS + s) * CCH + c) * (HH * WW * (NB / 2));

#pragma unroll 1
    for (int r7 = 0; r7 < 6; r7++) {
#pragma unroll
        for (int rr = 0; rr < 7; rr++) {
            int row = r7 * 7 + rr;
            if (row < RIN) {
                // ---- produce this warp's 16 iso positions (private slab) ----
                const float* crow = &sm.conv[row * POSP + 8 * w + xi];
                float cva = crow[0];
                float cvb = crow[8];
                float da0 = cva - cn0, da1 = cva - cn1;
                float db0 = cvb - cn0, db1 = cvb - cn1;
                float2 e1, e2;
                e1.x = nrm * __expf(kf * da0 * da0);
                e1.y = nrm * __expf(kf * da1 * da1);
                e2.x = nrm * __expf(kf * db0 * db0);
                e2.y = nrm * __expf(kf * db1 * db1);
                float2* ps = sm.priv[row & 1][w];
                ps[xi * 4 + p] = e1;
                ps[(xi + 8) * 4 + p] = e2;
                __syncwarp();

                // ---- horizontal window (tap0 = own register) ----
                const float2* wp8 = &ps[xi * 4 + p];
                float2 t1 = wp8[4],  t2 = wp8[8],  t3 = wp8[12];
                float2 t4 = wp8[16], t5 = wp8[20], t6 = wp8[24];
                float2 s0 = fadd2(e1, t6);
                float2 s1 = fadd2(t1, t5);
                float2 s2 = fadd2(t2, t4);

                float2 hv0 = fmul2(wk[0][3], t3);
                float2 hv1 = fmul2(wk[1][3], t3);
                float2 hv2 = fmul2(wk[2][3], t3);
                hv0 = ffma2(wk[0][0], s0, hv0);
                hv1 = ffma2(wk[1][0], s0, hv1);
                hv2 = ffma2(wk[2][0], s0, hv2);
                hv0 = ffma2(wk[0][1], s1, hv0);
                hv1 = ffma2(wk[1][1], s1, hv1);
                hv2 = ffma2(wk[2][1], s1, hv2);
                hv0 = ffma2(wk[0][2], s2, hv0);
                hv1 = ffma2(wk[1][2], s2, hv1);
                hv2 = ffma2(wk[2][2], s2, hv2);

                // alpha2: thread-private smem ring
                sm.h2[rr][tid] = hv2;

                // alphas 0,1: register scatter rings (stale slots are
                // re-initialized at t==0 before any store)
#pragma unroll
                for (int t = 0; t < 7; t++) {
                    const int slot = ((rr - t) % 7 + 7) % 7;
                    const int wi = (t < 4) ? t : 6 - t;
                    if (t == 0) {
                        acc[0][slot] = fmul2(wk[0][wi], hv0);
                        acc[1][slot] = fmul2(wk[1][wi], hv1);
                    } else {
                        acc[0][slot] = ffma2(wk[0][wi], hv0, acc[0][slot]);
                        acc[1][slot] = ffma2(wk[1][wi], hv1, acc[1][slot]);
                    }
                }

                // ---- completed output row y = row - 6 ----
                if (row >= 6) {
                    const int slot = (rr + 1) % 7;
                    float2 g0 = sm.h2[(rr + 1) % 7][tid];
                    float2 g1 = sm.h2[(rr + 2) % 7][tid];
                    float2 g2 = sm.h2[(rr + 3) % 7][tid];
                    float2 g3 = sm.h2[(rr + 4) % 7][tid];
                    float2 g4 = sm.h2[(rr + 5) % 7][tid];
                    float2 g5 = sm.h2[(rr + 6) % 7][tid];
                    float2 sA = fadd2(g0, hv2);
                    float2 sB = fadd2(g1, g5);
                    float2 sC = fadd2(g2, g4);
                    float2 o2 = fmul2(wk[2][3], g3);
                    o2 = ffma2(wk[2][0], sA, o2);
                    o2 = ffma2(wk[2][1], sB, o2);
                    o2 = ffma2(wk[2][2], sC, o2);

                    size_t off = ((size_t)(gy0 + row - 6) * WW + gx0 + 8 * w + xi)
                                 * (NB / 2) + p;
                    outb[off] = acc[0][slot];
                    outb[off + ASTR] = acc[1][slot];
                    outb[off + 2 * ASTR] = o2;
                }
            }
        }
    }
}

// ---------------------------------------------------------------------------
extern "C" void kernel_launch(void* const* d_in, const int* in_sizes, int n_in,
                              void* d_out, int out_size) {
    const float* im      = (const float*)d_in[0];   // (512,512,3)
    const float* sig2d   = (const float*)d_in[1];   // (2,9,9)
    const float* al2d    = (const float*)d_in[2];   // (3,7,7)
    const float* centers = (const float*)d_in[3];   // (8,)
    const float* betas   = (const float*)d_in[4];   // (2,)
    float* out = (float*)d_out;

    dim3 gs(WW / STW, HH / STH, CCH);
    k_sigma<<<gs, 256>>>(im, sig2d);
    dim3 g(WW / W_T, HH / H_T, CCH * SS * BB);
    k_loi<<<g, 256>>>(al2d, centers, betas, out);
}